// round 14
// baseline (speedup 1.0000x reference)
#include <cuda_runtime.h>
#include <cstdint>

// ForgetMult single-pass chunked scan with DEDICATED SPINE SCANNERS.
// h_t = f_t*x_t + (1-f_t)*h_{t-1}  ==  h_t = h_{t-1} + f_t*(x_t - h_{t-1})
//
// Grid = 32 scanner blocks (one per tile, dispatched first, persistent) +
// 4096 worker blocks (chunk-major). Workers: load chunk tile via cp.async,
// compute summary (a = prod(1-f), b = local scan), publish partial, then wait
// ONLY on the per-tile watermark and read g_inc[chunk-1] -> outputs. Scanners
// serially compose partials into inclusive states (windowed, ~100 cyc/hop),
// so the sequential chain runs concurrently with, not instead of, BW work.

#define FM_SEQ     2048
#define FM_NCH     16384
#define FM_NG      (FM_NCH / 2)              // 8192 float2 channel-groups
#define FM_L       16                        // timesteps per chunk
#define FM_NCHUNKS (FM_SEQ / FM_L)           // 128
#define FM_TPB     256                       // threads/block == groups per tile
#define FM_NTILES  (FM_NG / FM_TPB)          // 32
#define FM_NWORK   (FM_NCHUNKS * FM_NTILES)  // 4096
#define FM_W       8                         // scanner window (chunks)
#define FM_SMEM    (2 * FM_L * FM_TPB * 8)   // 64 KB worker tile

// Scratch (allocation-free rule: __device__ globals). ~50 MB total traffic.
__device__ float2 g_pa[FM_NCHUNKS][FM_NG];
__device__ float2 g_pb[FM_NCHUNKS][FM_NG];
__device__ float2 g_inc[FM_NCHUNKS][FM_NG];
__device__ int    g_pflag[FM_NCHUNKS][FM_NTILES];  // partial published
__device__ int    g_water[FM_NTILES * 32];         // watermark, 128B stride

__global__ void fm_init_flags()
{
    int i = blockIdx.x * blockDim.x + threadIdx.x;
    if (i < FM_NCHUNKS * FM_NTILES) ((int*)g_pflag)[i] = 0;
    if (i < FM_NTILES) g_water[i * 32] = -1;
}

__device__ __forceinline__ void cp_async8(void* s, const void* g)
{
    uint32_t sa = (uint32_t)__cvta_generic_to_shared(s);
    asm volatile("cp.async.ca.shared.global [%0], [%1], 8;\n" :: "r"(sa), "l"(g));
}

__device__ __forceinline__ int ld_acquire_gpu(const int* p)
{
    int v;
    asm volatile("ld.acquire.gpu.global.b32 %0, [%1];" : "=r"(v) : "l"(p) : "memory");
    return v;
}

__device__ __forceinline__ void st_release_gpu(int* p, int v)
{
    asm volatile("st.release.gpu.global.b32 [%0], %1;" :: "l"(p), "r"(v) : "memory");
}

__global__ __launch_bounds__(FM_TPB) void fm_fused(
    const float2* __restrict__ f, const float2* __restrict__ x,
    const float2* __restrict__ h0, float2* __restrict__ out)
{
    extern __shared__ float2 s_buf[];
    const int tid = threadIdx.x;

    if (blockIdx.x < FM_NTILES) {
        // ================= SCANNER (one block per tile) =================
        const int tile = blockIdx.x;
        const int g    = tile * FM_TPB + tid;

        float2 h = __ldg(h0 + g);

        for (int c0 = 0; c0 < FM_NCHUNKS; c0 += FM_W) {
            // Wait until all partials in window are published.
            for (;;) {
                int ready = 1;
#pragma unroll
                for (int j = 0; j < FM_W; j++)
                    ready &= (ld_acquire_gpu(&g_pflag[c0 + j][tile]) != 0);
                if (ready) break;
                __nanosleep(32);
            }
            // Compose window: loads hoisted by unroll, serial FMA chain.
#pragma unroll
            for (int j = 0; j < FM_W; j++) {
                const float2 a = g_pa[c0 + j][g];
                const float2 b = g_pb[c0 + j][g];
                h.x = fmaf(a.x, h.x, b.x);
                h.y = fmaf(a.y, h.y, b.y);
                g_inc[c0 + j][g] = h;
            }
            __syncthreads();
            if (tid == 0) st_release_gpu(&g_water[tile * 32], c0 + FM_W - 1);
        }
        return;
    }

    // ================= WORKER =================
    const int wi    = blockIdx.x - FM_NTILES;   // chunk-major
    const int chunk = wi / FM_NTILES;
    const int tile  = wi % FM_NTILES;
    const int g     = tile * FM_TPB + tid;

    float2* sf = s_buf;                    // [FM_L][FM_TPB]
    float2* sx = s_buf + FM_L * FM_TPB;

    const size_t base = (size_t)chunk * FM_L * FM_NG + g;

    // ---- Async-load chunk tile. Each thread later reads ONLY slots it wrote,
    // so wait_group alone suffices (no barrier).
#pragma unroll
    for (int t = 0; t < FM_L; t++) {
        cp_async8(&sf[t * FM_TPB + tid], f + base + (size_t)t * FM_NG);
        cp_async8(&sx[t * FM_TPB + tid], x + base + (size_t)t * FM_NG);
    }
    asm volatile("cp.async.commit_group;\n" ::: "memory");
    asm volatile("cp.async.wait_group 0;\n" ::: "memory");

    // ---- Chunk summary: a = prod(1-f), b = local scan from 0.
    float2 a = make_float2(1.f, 1.f);
    float2 b = make_float2(0.f, 0.f);
#pragma unroll
    for (int t = 0; t < FM_L; t++) {
        const float2 ft = sf[t * FM_TPB + tid];
        const float2 xt = sx[t * FM_TPB + tid];
        b.x = fmaf(ft.x, xt.x - b.x, b.x);  a.x *= (1.f - ft.x);
        b.y = fmaf(ft.y, xt.y - b.y, b.y);  a.y *= (1.f - ft.y);
    }

    // ---- Publish partial BEFORE any waiting (deadlock-freedom invariant).
    g_pa[chunk][g] = a;
    g_pb[chunk][g] = b;
    __syncthreads();
    if (tid == 0) st_release_gpu(&g_pflag[chunk][tile], 1);

    // ---- Wait for spine: single watermark poll, then one g_inc read.
    float2 hstart;
    if (chunk == 0) {
        hstart = __ldg(h0 + g);
    } else {
        while (ld_acquire_gpu(&g_water[tile * 32]) < chunk - 1)
            __nanosleep(64);
        hstart = g_inc[chunk - 1][g];
    }

    // ---- Output: exact forward recurrence from smem, streamed stores.
    float2 h = hstart;
#pragma unroll
    for (int t = 0; t < FM_L; t++) {
        const float2 ft = sf[t * FM_TPB + tid];
        const float2 xt = sx[t * FM_TPB + tid];
        h.x = fmaf(ft.x, xt.x - h.x, h.x);
        h.y = fmaf(ft.y, xt.y - h.y, h.y);
        __stcs(out + base + (size_t)t * FM_NG, h);
    }
}

// ---------------- Fallback: naive per-channel scan (unexpected shapes) ----------------
__global__ void fm_naive(const float* __restrict__ f, const float* __restrict__ x,
                         const float* __restrict__ h0, float* __restrict__ out,
                         int seq, int nch)
{
    int c = blockIdx.x * blockDim.x + threadIdx.x;
    if (c >= nch) return;
    float h = h0[c];
    for (int t = 0; t < seq; t++) {
        const float ft = f[(size_t)t * nch + c];
        h = fmaf(1.f - ft, h, ft * x[(size_t)t * nch + c]);
        out[(size_t)t * nch + c] = h;
    }
}

extern "C" void kernel_launch(void* const* d_in, const int* in_sizes, int n_in,
                              void* d_out, int out_size)
{
    const float* f  = (const float*)d_in[0];
    const float* x  = (const float*)d_in[1];
    const float* h0 = (const float*)d_in[2];
    float* out      = (float*)d_out;

    const int nch = in_sizes[2];
    const int seq = in_sizes[0] / nch;

    if (seq == FM_SEQ && nch == FM_NCH) {
        cudaFuncSetAttribute(fm_fused, cudaFuncAttributeMaxDynamicSharedMemorySize,
                             FM_SMEM);
        fm_init_flags<<<(FM_NWORK + 255) / 256, 256>>>();
        fm_fused<<<FM_NTILES + FM_NWORK, FM_TPB, FM_SMEM>>>(
            (const float2*)f, (const float2*)x, (const float2*)h0, (float2*)out);
    } else {
        int tpb = 128;
        fm_naive<<<(nch + tpb - 1) / tpb, tpb>>>(f, x, h0, out, seq, nch);
    }
}

// round 15
// speedup vs baseline: 1.1867x; 1.1867x over previous
#include <cuda_runtime.h>
#include <cstdint>

// ForgetMult single-pass chunked scan — R4 engine + superchunk decomposition.
// h_t = f_t*x_t + (1-f_t)*h_{t-1}  ==  h_t = h_{t-1} + f_t*(x_t - h_{t-1})
//
// 256 chunks of L=8, grouped into 16 superchunks of 16. Serial dependency
// exists ONLY between superchunks (16 hops, published by the last chunk of
// each superchunk). Within a superchunk, each chunk resolves from the
// superchunk-start state plus its predecessors' PARTIAL summaries, which are
// published as soon as each block's loads land (no chain). Memory engine is
// the proven R4 config: TPB=128, float4 lanes, 32 KB cp.async tile.

#define FM_SEQ     2048
#define FM_NCH     16384
#define FM_NG      (FM_NCH / 4)              // 4096 float4 channel-groups
#define FM_L       8                         // timesteps per chunk
#define FM_NCHUNKS (FM_SEQ / FM_L)           // 256
#define FM_SUPER   16                        // chunks per superchunk
#define FM_NSUPER  (FM_NCHUNKS / FM_SUPER)   // 16
#define FM_TPB     128                       // threads/block == groups per tile
#define FM_NTILES  (FM_NG / FM_TPB)          // 32
#define FM_NBLK    (FM_NCHUNKS * FM_NTILES)  // 8192

// Scratch (allocation-free rule: __device__ globals). ~33 MB, L2-resident.
__device__ float4 g_pa[FM_NCHUNKS][FM_NG];       // partial a = prod(1-f)
__device__ float4 g_pb[FM_NCHUNKS][FM_NG];       // partial b = local scan
__device__ float4 g_sstart[FM_NSUPER][FM_NG];    // state at superchunk start
__device__ int    g_pflag[FM_NCHUNKS][FM_NTILES];
__device__ int    g_sflag[FM_NSUPER][FM_NTILES];

__global__ void fm_init_flags()
{
    int i = blockIdx.x * blockDim.x + threadIdx.x;
    if (i < FM_NCHUNKS * FM_NTILES) ((int*)g_pflag)[i] = 0;
    if (i < FM_NSUPER * FM_NTILES)  ((int*)g_sflag)[i] = 0;
}

__device__ __forceinline__ void cp_async16(void* s, const void* g)
{
    uint32_t sa = (uint32_t)__cvta_generic_to_shared(s);
    asm volatile("cp.async.cg.shared.global [%0], [%1], 16;\n" :: "r"(sa), "l"(g));
}

__device__ __forceinline__ int ld_acquire_gpu(const int* p)
{
    int v;
    asm volatile("ld.acquire.gpu.global.b32 %0, [%1];" : "=r"(v) : "l"(p) : "memory");
    return v;
}

__device__ __forceinline__ void st_release_gpu(int* p, int v)
{
    asm volatile("st.release.gpu.global.b32 [%0], %1;" :: "l"(p), "r"(v) : "memory");
}

__global__ __launch_bounds__(FM_TPB) void fm_fused(
    const float4* __restrict__ f, const float4* __restrict__ x,
    const float4* __restrict__ h0, float4* __restrict__ out)
{
    // chunk-major bids: all dependencies point to strictly lower block IDs
    // (intra-superchunk partials and previous superchunk's last chunk), so
    // in-order dispatch guarantees progress.
    const int chunk  = blockIdx.x / FM_NTILES;
    const int tile   = blockIdx.x % FM_NTILES;
    const int tid    = threadIdx.x;
    const int g      = tile * FM_TPB + tid;
    const int s      = chunk / FM_SUPER;        // superchunk id
    const int o      = chunk % FM_SUPER;        // offset within superchunk
    const int sbase  = s * FM_SUPER;            // first chunk of superchunk

    __shared__ float4 sf[FM_L * FM_TPB];
    __shared__ float4 sx[FM_L * FM_TPB];

    const size_t base = (size_t)chunk * FM_L * FM_NG + g;

    // ---- Async-load chunk tile. Each thread later reads ONLY slots it wrote,
    // so wait_group alone suffices (no barrier needed).
#pragma unroll
    for (int t = 0; t < FM_L; t++) {
        cp_async16(&sf[t * FM_TPB + tid], f + base + (size_t)t * FM_NG);
        cp_async16(&sx[t * FM_TPB + tid], x + base + (size_t)t * FM_NG);
    }
    asm volatile("cp.async.commit_group;\n" ::: "memory");
    asm volatile("cp.async.wait_group 0;\n" ::: "memory");

    // ---- Chunk summary: a = prod(1-f), b = local scan from 0.
    float4 a = make_float4(1.f, 1.f, 1.f, 1.f);
    float4 b = make_float4(0.f, 0.f, 0.f, 0.f);
#pragma unroll
    for (int t = 0; t < FM_L; t++) {
        const float4 ft = sf[t * FM_TPB + tid];
        const float4 xt = sx[t * FM_TPB + tid];
        b.x = fmaf(ft.x, xt.x - b.x, b.x);  a.x *= (1.f - ft.x);
        b.y = fmaf(ft.y, xt.y - b.y, b.y);  a.y *= (1.f - ft.y);
        b.z = fmaf(ft.z, xt.z - b.z, b.z);  a.z *= (1.f - ft.z);
        b.w = fmaf(ft.w, xt.w - b.w, b.w);  a.w *= (1.f - ft.w);
    }

    // ---- Publish partial BEFORE any waiting (progress invariant).
    if (o != FM_SUPER - 1) {                 // last-of-superchunk publishes sstart instead
        g_pa[chunk][g] = a;
        g_pb[chunk][g] = b;
        __syncthreads();
        if (tid == 0) st_release_gpu(&g_pflag[chunk][tile], 1);
    }

    // ---- Wait: superchunk-start flag + intra-superchunk predecessor partials.
    // Thread tid<o spins on partial flag of chunk sbase+tid; thread o spins on
    // the superchunk-start flag. All converge at the barrier.
    if (tid < o) {
        while (ld_acquire_gpu(&g_pflag[sbase + tid][tile]) == 0) __nanosleep(32);
    } else if (tid == o && s > 0) {
        while (ld_acquire_gpu(&g_sflag[s][tile]) == 0) __nanosleep(32);
    }
    __syncthreads();

    // ---- Compose h_start = partials(sbase..chunk-1) applied to sstart.
    float4 h = (s > 0) ? g_sstart[s][g] : __ldg(h0 + g);
    for (int j0 = 0; j0 < o; j0 += 4) {
        float4 ta[4], tb[4];
        const int m = (o - j0 < 4) ? (o - j0) : 4;
#pragma unroll
        for (int k = 0; k < 4; k++)
            if (k < m) { ta[k] = g_pa[sbase + j0 + k][g]; tb[k] = g_pb[sbase + j0 + k][g]; }
#pragma unroll
        for (int k = 0; k < 4; k++)
            if (k < m) {
                h.x = fmaf(ta[k].x, h.x, tb[k].x);
                h.y = fmaf(ta[k].y, h.y, tb[k].y);
                h.z = fmaf(ta[k].z, h.z, tb[k].z);
                h.w = fmaf(ta[k].w, h.w, tb[k].w);
            }
    }
    const float4 hstart = h;

    // ---- Last chunk of superchunk: publish next superchunk's start state.
    if (o == FM_SUPER - 1 && s < FM_NSUPER - 1) {
        float4 he;
        he.x = fmaf(a.x, hstart.x, b.x);
        he.y = fmaf(a.y, hstart.y, b.y);
        he.z = fmaf(a.z, hstart.z, b.z);
        he.w = fmaf(a.w, hstart.w, b.w);
        g_sstart[s + 1][g] = he;
        __syncthreads();
        if (tid == 0) st_release_gpu(&g_sflag[s + 1][tile], 1);
    }

    // ---- Output: exact forward recurrence from smem, streamed stores.
    h = hstart;
#pragma unroll
    for (int t = 0; t < FM_L; t++) {
        const float4 ft = sf[t * FM_TPB + tid];
        const float4 xt = sx[t * FM_TPB + tid];
        h.x = fmaf(ft.x, xt.x - h.x, h.x);
        h.y = fmaf(ft.y, xt.y - h.y, h.y);
        h.z = fmaf(ft.z, xt.z - h.z, h.z);
        h.w = fmaf(ft.w, xt.w - h.w, h.w);
        __stcs(out + base + (size_t)t * FM_NG, h);
    }
}

// ---------------- Fallback: naive per-channel scan (unexpected shapes) ----------------
__global__ void fm_naive(const float* __restrict__ f, const float* __restrict__ x,
                         const float* __restrict__ h0, float* __restrict__ out,
                         int seq, int nch)
{
    int c = blockIdx.x * blockDim.x + threadIdx.x;
    if (c >= nch) return;
    float h = h0[c];
    for (int t = 0; t < seq; t++) {
        const float ft = f[(size_t)t * nch + c];
        h = fmaf(1.f - ft, h, ft * x[(size_t)t * nch + c]);
        out[(size_t)t * nch + c] = h;
    }
}

extern "C" void kernel_launch(void* const* d_in, const int* in_sizes, int n_in,
                              void* d_out, int out_size)
{
    const float* f  = (const float*)d_in[0];
    const float* x  = (const float*)d_in[1];
    const float* h0 = (const float*)d_in[2];
    float* out      = (float*)d_out;

    const int nch = in_sizes[2];
    const int seq = in_sizes[0] / nch;

    if (seq == FM_SEQ && nch == FM_NCH) {
        fm_init_flags<<<(FM_NCHUNKS * FM_NTILES + 255) / 256, 256>>>();
        fm_fused<<<FM_NBLK, FM_TPB>>>(
            (const float4*)f, (const float4*)x, (const float4*)h0, (float4*)out);
    } else {
        int tpb = 128;
        fm_naive<<<(nch + tpb - 1) / tpb, tpb>>>(f, x, h0, out, seq, nch);
    }
}